// round 1
// baseline (speedup 1.0000x reference)
#include <cuda_runtime.h>

// SpanIndexEncoder: out[t,f] = sum over nodes n (n < num_nodes, start_n <= t <= end_n) of emb[n,f]
// Implemented as difference-array scatter + chunked prefix scan along t.
//   T = 8192 tokens, N = 8192 max nodes, F = 256 features.

#define T_MAX  8192
#define N_MAX  8192
#define FDIM   256
#define CHUNK  64
#define NCHUNK (T_MAX / CHUNK)   // 128

// Scratch (allocation-free): 8 MB diff array + 128 KB chunk sums.
__device__ float g_diff[T_MAX * FDIM];
__device__ float g_S[NCHUNK * FDIM];

// ---------------------------------------------------------------------------
// K1: zero the diff array (must be re-zeroed every replay).
// ---------------------------------------------------------------------------
__global__ void k_zero() {
    int i = blockIdx.x * blockDim.x + threadIdx.x;
    reinterpret_cast<float4*>(g_diff)[i] = make_float4(0.f, 0.f, 0.f, 0.f);
}

// ---------------------------------------------------------------------------
// K2: scatter. One block per node, one thread per feature.
//   diff[start][f]  += emb[n][f]
//   diff[end+1][f]  -= emb[n][f]   (skip if end+1 == T_MAX)
// Atomics are spread over ~4096+8192 distinct rows x 256 features -> low
// contention; ptxas emits REDG (no return) for atomicAdd whose result is
// unused.
// ---------------------------------------------------------------------------
__global__ void k_scatter(const float* __restrict__ emb,
                          const int*   __restrict__ starts,
                          const int*   __restrict__ ends,
                          const int*   __restrict__ num_nodes_p) {
    int n = blockIdx.x;
    if (n >= *num_nodes_p) return;
    int s = starts[n];
    int e = ends[n];
    if (s > e) return;                       // empty span contributes nothing
    int f = threadIdx.x;
    float v = emb[n * FDIM + f];
    atomicAdd(&g_diff[s * FDIM + f], v);
    int e1 = e + 1;
    if (e1 < T_MAX) atomicAdd(&g_diff[e1 * FDIM + f], -v);
}

// ---------------------------------------------------------------------------
// K3: per-chunk column sums. Block c, thread f: S[c][f] = sum over chunk rows.
// 64 independent coalesced loads per thread -> deep MLP, L2-resident.
// ---------------------------------------------------------------------------
__global__ void k_sums() {
    int c = blockIdx.x;
    int f = threadIdx.x;
    const float* base = g_diff + c * CHUNK * FDIM + f;
    float s = 0.f;
#pragma unroll
    for (int t = 0; t < CHUNK; t++) s += base[t * FDIM];
    g_S[c * FDIM + f] = s;
}

// ---------------------------------------------------------------------------
// K4: final scan. Block c, thread f:
//   acc = sum of S[0..c-1][f]  (chunk-exclusive prefix, L2-hit coalesced)
//   then serial inclusive scan of the chunk, writing out.
// ---------------------------------------------------------------------------
__global__ void k_out(float* __restrict__ out) {
    int c = blockIdx.x;
    int f = threadIdx.x;
    float acc = 0.f;
    for (int cc = 0; cc < c; cc++) acc += g_S[cc * FDIM + f];
    const float* base = g_diff + c * CHUNK * FDIM + f;
    float*       ob   = out    + c * CHUNK * FDIM + f;
#pragma unroll
    for (int t = 0; t < CHUNK; t++) {
        acc += base[t * FDIM];
        ob[t * FDIM] = acc;
    }
}

// ---------------------------------------------------------------------------
// Inputs (metadata order): embedding f32 [8192*256], node_span_starts i32
// [8192], node_span_ends i32 [8192], num_nodes i32 [1]. Output f32 [8192*256].
// ---------------------------------------------------------------------------
extern "C" void kernel_launch(void* const* d_in, const int* in_sizes, int n_in,
                              void* d_out, int out_size) {
    const float* emb    = (const float*)d_in[0];
    const int*   starts = (const int*)d_in[1];
    const int*   ends   = (const int*)d_in[2];
    const int*   nn     = (const int*)d_in[3];
    float*       out    = (float*)d_out;

    // zero 8 MB diff: T_MAX*FDIM/4 float4 = 524288 -> 2048 blocks x 256
    k_zero<<<(T_MAX * FDIM / 4) / 256, 256>>>();
    k_scatter<<<N_MAX, FDIM>>>(emb, starts, ends, nn);
    k_sums<<<NCHUNK, FDIM>>>();
    k_out<<<NCHUNK, FDIM>>>(out);
}